// round 5
// baseline (speedup 1.0000x reference)
#include <cuda_runtime.h>
#include <cuda_fp16.h>
#include <mma.h>
#include <cstdint>

using namespace nvcuda;

#define N_NODES 50000
#define N_EDGES 800000
#define F 128
#define GRM 64                  // M-tile (nodes per fused block)
#define LDA 136                 // padded leading dim (halves) for A tile
#define CSR_T 1024
#define PER ((N_NODES + CSR_T - 1) / CSR_T)   // 49
#define SMEM_FUSED (GRM * LDA * 2)            // 17408 bytes

// ---- scratch (no allocation allowed -> __device__ globals) ----
// NOTE: deg/vec are zeroed by k_tail at the END of each launch sequence
// (module zero-init covers the very first execution).
__device__ int    g_deg_src[N_NODES];
__device__ int    g_deg_dst[N_NODES];
__device__ float  g_out_norm[N_NODES];
__device__ float  g_in_norm[N_NODES];
__device__ int    g_row_ptr[N_NODES + 1];
__device__ int    g_cursor[N_NODES];
__device__ int    g_col_idx[N_EDGES];
__device__ __half g_x0[N_NODES * F];   // feat * out_norm, fp16
__device__ __half g_x1[N_NODES * F];
__device__ __half g_x2[N_NODES * F];
__device__ __half g_w1h[F * F];
__device__ __half g_w2h[F * F];
__device__ float  g_vec[F];

// ---------------- setup ----------------
__global__ void k_count(const int* __restrict__ src, const int* __restrict__ dst) {
    int e = blockIdx.x * blockDim.x + threadIdx.x;
    if (e < N_EDGES) {
        atomicAdd(&g_deg_src[src[e]], 1);
        atomicAdd(&g_deg_dst[dst[e]], 1);
    }
}

// single-block CSR builder: prefix sum of deg_dst + norms + cursor init
__global__ void k_csr() {
    __shared__ int s[CSR_T];
    int t = threadIdx.x;
    int base = t * PER;
    int sum = 0;
    for (int j = 0; j < PER; j++) {
        int i = base + j;
        if (i < N_NODES) sum += g_deg_dst[i];
    }
    s[t] = sum;
    __syncthreads();
    for (int off = 1; off < CSR_T; off <<= 1) {
        int x = 0;
        if (t >= off) x = s[t - off];
        __syncthreads();
        if (t >= off) s[t] += x;
        __syncthreads();
    }
    int run = s[t] - sum;   // exclusive prefix
    for (int j = 0; j < PER; j++) {
        int i = base + j;
        if (i < N_NODES) {
            int d = g_deg_dst[i];
            g_row_ptr[i] = run;
            g_cursor[i] = run;
            run += d;
            g_in_norm[i]  = rsqrtf((float)max(d, 1));
            g_out_norm[i] = rsqrtf((float)max(g_deg_src[i], 1));
        }
    }
    if (t == CSR_T - 1) g_row_ptr[N_NODES] = s[t];
}

// CSR fill + feat->fp16 prescale + W1/W2 -> fp16, all independent given k_csr
__global__ void k_fill_prep(const int* __restrict__ src, const int* __restrict__ dst,
                            const float* __restrict__ feat,
                            const float* __restrict__ W1, const float* __restrict__ W2) {
    int i = blockIdx.x * blockDim.x + threadIdx.x;
    if (i < N_EDGES) {
        int d = dst[i];
        int p = atomicAdd(&g_cursor[d], 1);
        g_col_idx[p] = src[i];
    }
    if (i < N_NODES * F / 4) {
        int base = i * 4;
        float on = g_out_norm[base >> 7];
        float4 v = *(const float4*)&feat[base];
        __half2 h01 = __floats2half2_rn(v.x * on, v.y * on);
        __half2 h23 = __floats2half2_rn(v.z * on, v.w * on);
        uint2 pk;
        pk.x = *(uint32_t*)&h01;
        pk.y = *(uint32_t*)&h23;
        *(uint2*)&g_x0[base] = pk;
    }
    if (i < F * F) {
        g_w1h[i] = __float2half(W1[i]);
        g_w2h[i] = __float2half(W2[i]);
    }
}

// ---------------- fused layer: gather -> smem fp16 -> wmma HMMA -> epilogue ----
// 256 threads (8 warps), 64 nodes/block. smem = A tile [64][LDA] fp16 only;
// W read as fp16 directly from global (L1/L2 resident). Epilogue reuses smem.
__global__ void __launch_bounds__(256, 3)
k_fused(const __half* __restrict__ x, const __half* __restrict__ wh,
        const float* __restrict__ b, __half* __restrict__ y) {
    extern __shared__ char smem[];
    __half* sA = (__half*)smem;             // [64][LDA]
    int t = threadIdx.x, warp = t >> 5, lane = t & 31;
    int row0 = blockIdx.x * GRM;

    // gather: warp per node, 8 rounds, edge loop unrolled x4 for MLP
    const uint2* x2 = (const uint2*)x;
    const int* __restrict__ ci = g_col_idx;
#pragma unroll 1
    for (int r = 0; r < 8; r++) {
        int lr = r * 8 + warp;
        int node = row0 + lr;
        float4 a0 = {0.f, 0.f, 0.f, 0.f};
        float4 a1 = {0.f, 0.f, 0.f, 0.f};
        if (node < N_NODES) {
            int beg = g_row_ptr[node], end = g_row_ptr[node + 1];
            int e = beg;
            for (; e + 4 <= end; e += 4) {
                int s0 = ci[e], s1 = ci[e + 1], s2 = ci[e + 2], s3 = ci[e + 3];
                uint2 v0 = x2[s0 * 32 + lane];
                uint2 v1 = x2[s1 * 32 + lane];
                uint2 v2 = x2[s2 * 32 + lane];
                uint2 v3 = x2[s3 * 32 + lane];
                float2 p0a = __half22float2(*(__half2*)&v0.x), p0b = __half22float2(*(__half2*)&v0.y);
                float2 p1a = __half22float2(*(__half2*)&v1.x), p1b = __half22float2(*(__half2*)&v1.y);
                float2 p2a = __half22float2(*(__half2*)&v2.x), p2b = __half22float2(*(__half2*)&v2.y);
                float2 p3a = __half22float2(*(__half2*)&v3.x), p3b = __half22float2(*(__half2*)&v3.y);
                a0.x += p0a.x; a0.y += p0a.y; a0.z += p0b.x; a0.w += p0b.y;
                a1.x += p1a.x; a1.y += p1a.y; a1.z += p1b.x; a1.w += p1b.y;
                a0.x += p2a.x; a0.y += p2a.y; a0.z += p2b.x; a0.w += p2b.y;
                a1.x += p3a.x; a1.y += p3a.y; a1.z += p3b.x; a1.w += p3b.y;
            }
            for (; e < end; e++) {
                int s0 = ci[e];
                uint2 v0 = x2[s0 * 32 + lane];
                float2 pa = __half22float2(*(__half2*)&v0.x), pb = __half22float2(*(__half2*)&v0.y);
                a0.x += pa.x; a0.y += pa.y; a0.z += pb.x; a0.w += pb.y;
            }
            float sc = g_in_norm[node];
            a0.x = (a0.x + a1.x) * sc;
            a0.y = (a0.y + a1.y) * sc;
            a0.z = (a0.z + a1.z) * sc;
            a0.w = (a0.w + a1.w) * sc;
        }
        __half2 h01 = __floats2half2_rn(a0.x, a0.y);
        __half2 h23 = __floats2half2_rn(a0.z, a0.w);
        uint2 pk;
        pk.x = *(uint32_t*)&h01;
        pk.y = *(uint32_t*)&h23;
        *(uint2*)&sA[lr * LDA + lane * 4] = pk;
    }
    __syncthreads();

    // GEMM: warp (wy, wx): rows wy*32..+31, cols wx*32..+31; B from global fp16
    int wy = warp >> 2, wx = warp & 3;
    wmma::fragment<wmma::accumulator, 16, 16, 16, float> c[2][2];
#pragma unroll
    for (int i = 0; i < 2; i++)
#pragma unroll
        for (int j = 0; j < 2; j++) wmma::fill_fragment(c[i][j], 0.f);

#pragma unroll
    for (int k0 = 0; k0 < F; k0 += 16) {
        wmma::fragment<wmma::matrix_a, 16, 16, 16, __half, wmma::row_major> af[2];
        wmma::fragment<wmma::matrix_b, 16, 16, 16, __half, wmma::row_major> bf[2];
#pragma unroll
        for (int i = 0; i < 2; i++)
            wmma::load_matrix_sync(af[i], &sA[(wy * 32 + i * 16) * LDA + k0], LDA);
#pragma unroll
        for (int j = 0; j < 2; j++)
            wmma::load_matrix_sync(bf[j], &wh[k0 * F + wx * 32 + j * 16], F);
#pragma unroll
        for (int i = 0; i < 2; i++)
#pragma unroll
            for (int j = 0; j < 2; j++)
                wmma::mma_sync(c[i][j], af[i], bf[j], c[i][j]);
    }
    __syncthreads();   // done reading sA; reuse as epilogue scratch

    float* wscr = (float*)smem + warp * (16 * 20);   // 1280B per warp
#pragma unroll
    for (int i = 0; i < 2; i++) {
#pragma unroll
        for (int j = 0; j < 2; j++) {
            wmma::store_matrix_sync(wscr, c[i][j], 20, wmma::mem_row_major);
            __syncwarp();
            if (lane < 16) {
                int grow = row0 + wy * 32 + i * 16 + lane;
                if (grow < N_NODES) {
                    float on = g_out_norm[grow];
                    const float* cr = &wscr[lane * 20];
                    __half2 hv[8];
#pragma unroll
                    for (int cc = 0; cc < 16; cc += 4) {
                        float4 bv = *(const float4*)&b[wx * 32 + j * 16 + cc];
                        float v0 = fmaxf(cr[cc]     + bv.x, 0.f) * on;
                        float v1 = fmaxf(cr[cc + 1] + bv.y, 0.f) * on;
                        float v2 = fmaxf(cr[cc + 2] + bv.z, 0.f) * on;
                        float v3 = fmaxf(cr[cc + 3] + bv.w, 0.f) * on;
                        hv[cc / 2]     = __floats2half2_rn(v0, v1);
                        hv[cc / 2 + 1] = __floats2half2_rn(v2, v3);
                    }
                    uint4* dstp = (uint4*)(y + (size_t)grow * F + wx * 32 + j * 16);
                    dstp[0] = *(uint4*)&hv[0];
                    dstp[1] = *(uint4*)&hv[4];
                }
            }
            __syncwarp();
        }
    }
}

// layer-3 aggregation folded into a 128-vector (x already prescaled by out_norm):
// g_vec = (1/N) * sum_i in_norm[i] * sum_{e: dst=i} x[src]
__global__ void k_agg3(const __half* __restrict__ x) {
    __shared__ float sacc[F];
    int t = threadIdx.x;
    if (t < F) sacc[t] = 0.f;
    __syncthreads();
    int w = (blockIdx.x * blockDim.x + t) >> 5;
    int lane = t & 31;
    if (w < N_NODES) {
        int beg = g_row_ptr[w], end = g_row_ptr[w + 1];
        const uint2* x2 = (const uint2*)x;
        const int* __restrict__ ci = g_col_idx;
        float4 a0 = {0.f, 0.f, 0.f, 0.f};
        float4 a1 = {0.f, 0.f, 0.f, 0.f};
        int e = beg;
        for (; e + 4 <= end; e += 4) {
            int s0 = ci[e], s1 = ci[e + 1], s2 = ci[e + 2], s3 = ci[e + 3];
            uint2 v0 = x2[s0 * 32 + lane];
            uint2 v1 = x2[s1 * 32 + lane];
            uint2 v2 = x2[s2 * 32 + lane];
            uint2 v3 = x2[s3 * 32 + lane];
            float2 p0a = __half22float2(*(__half2*)&v0.x), p0b = __half22float2(*(__half2*)&v0.y);
            float2 p1a = __half22float2(*(__half2*)&v1.x), p1b = __half22float2(*(__half2*)&v1.y);
            float2 p2a = __half22float2(*(__half2*)&v2.x), p2b = __half22float2(*(__half2*)&v2.y);
            float2 p3a = __half22float2(*(__half2*)&v3.x), p3b = __half22float2(*(__half2*)&v3.y);
            a0.x += p0a.x; a0.y += p0a.y; a0.z += p0b.x; a0.w += p0b.y;
            a1.x += p1a.x; a1.y += p1a.y; a1.z += p1b.x; a1.w += p1b.y;
            a0.x += p2a.x; a0.y += p2a.y; a0.z += p2b.x; a0.w += p2b.y;
            a1.x += p3a.x; a1.y += p3a.y; a1.z += p3b.x; a1.w += p3b.y;
        }
        for (; e < end; e++) {
            int s0 = ci[e];
            uint2 v0 = x2[s0 * 32 + lane];
            float2 pa = __half22float2(*(__half2*)&v0.x), pb = __half22float2(*(__half2*)&v0.y);
            a0.x += pa.x; a0.y += pa.y; a0.z += pb.x; a0.w += pb.y;
        }
        float sc = g_in_norm[w] * (1.0f / N_NODES);
        atomicAdd(&sacc[lane * 4 + 0], (a0.x + a1.x) * sc);
        atomicAdd(&sacc[lane * 4 + 1], (a0.y + a1.y) * sc);
        atomicAdd(&sacc[lane * 4 + 2], (a0.z + a1.z) * sc);
        atomicAdd(&sacc[lane * 4 + 3], (a0.w + a1.w) * sc);
    }
    __syncthreads();
    if (t < F) atomicAdd(&g_vec[t], sacc[t]);
}

// final 128x128 matvec: out = g_vec @ W3 + b3 (fp32)
__global__ void k_final(const float* __restrict__ W3, const float* __restrict__ b3,
                        float* __restrict__ out) {
    __shared__ float sv[F];
    int j = threadIdx.x;
    sv[j] = g_vec[j];
    __syncthreads();
    float acc = b3[j];
#pragma unroll 8
    for (int k = 0; k < F; k++) acc += sv[k] * W3[k * F + j];
    out[j] = acc;
}

// zero state for NEXT replay (module zero-init covers the first run)
__global__ void k_tail() {
    int i = blockIdx.x * blockDim.x + threadIdx.x;
    if (i < N_NODES) { g_deg_src[i] = 0; g_deg_dst[i] = 0; }
    if (i < F) g_vec[i] = 0.f;
}

extern "C" void kernel_launch(void* const* d_in, const int* in_sizes, int n_in,
                              void* d_out, int out_size) {
    const float* feat = (const float*)d_in[0];
    const float* W1   = (const float*)d_in[1];
    const float* b1   = (const float*)d_in[2];
    const float* W2   = (const float*)d_in[3];
    const float* b2   = (const float*)d_in[4];
    const float* W3   = (const float*)d_in[5];
    const float* b3   = (const float*)d_in[6];
    const int*   src  = (const int*)d_in[7];
    const int*   dst  = (const int*)d_in[8];
    float* out = (float*)d_out;

    void *p0, *p1, *p2, *pw1, *pw2;
    cudaGetSymbolAddress(&p0, g_x0);
    cudaGetSymbolAddress(&p1, g_x1);
    cudaGetSymbolAddress(&p2, g_x2);
    cudaGetSymbolAddress(&pw1, g_w1h);
    cudaGetSymbolAddress(&pw2, g_w2h);
    __half* x0 = (__half*)p0;
    __half* x1 = (__half*)p1;
    __half* x2 = (__half*)p2;
    __half* w1h = (__half*)pw1;
    __half* w2h = (__half*)pw2;

    int nb_nodes = (N_NODES + 255) / 256;
    int nb_edges = (N_EDGES + 255) / 256;
    int nb_agg   = (N_NODES * 32 + 255) / 256;
    int nb_fused = (N_NODES + GRM - 1) / GRM;            // 782
    int nb_fp    = (N_NODES * F / 4 + 255) / 256;        // covers edges too (1.6M > 800k)

    // 1: degrees (deg arrays pre-zeroed by k_tail of previous run / module init)
    k_count<<<nb_edges, 256>>>(src, dst);
    // 2: CSR offsets + norms
    k_csr<<<1, CSR_T>>>();
    // 3: CSR fill + fp16 prescaled features + fp16 weights
    k_fill_prep<<<nb_fp, 256>>>(src, dst, feat, W1, W2);
    // 4: layer 1 (profiled by ncu)
    k_fused<<<nb_fused, 256, SMEM_FUSED>>>(x0, w1h, b1, x1);
    // 5: layer 2
    k_fused<<<nb_fused, 256, SMEM_FUSED>>>(x1, w2h, b2, x2);
    // 6: layer 3 gather folded into mean
    k_agg3<<<nb_agg, 256>>>(x2);
    // 7: final matvec
    k_final<<<1, F>>>(W3, b3, out);
    // 8: re-zero state for next replay
    k_tail<<<nb_nodes, 256>>>();
}

// round 6
// speedup vs baseline: 1.0780x; 1.0780x over previous
#include <cuda_runtime.h>
#include <cuda_fp16.h>
#include <mma.h>
#include <cstdint>

using namespace nvcuda;

#define N_NODES 50000
#define N_EDGES 800000
#define F 128
#define GRM 64                  // rows per GEMM block
#define LDA 136                 // padded leading dim (halves)
#define CSR_T 1024
#define PER ((N_NODES + CSR_T - 1) / CSR_T)   // 49
#define SMEM_GEMM (GRM * LDA * 2)             // 17408 bytes

// ---- scratch (no allocation allowed -> __device__ globals) ----
// deg/vec zeroed by k_tail at END of each replay (module zero-init covers run 1)
__device__ int    g_deg_src[N_NODES];
__device__ int    g_deg_dst[N_NODES];
__device__ float  g_out_norm[N_NODES];
__device__ float  g_in_norm[N_NODES];
__device__ int    g_row_ptr[N_NODES + 1];
__device__ int    g_cursor[N_NODES];
__device__ int    g_col_idx[N_EDGES];
__device__ __half g_x0[N_NODES * F];   // feat * out_norm, fp16
__device__ __half g_x1[N_NODES * F];
__device__ __half g_x2[N_NODES * F];
__device__ __half g_m[N_NODES * F];    // aggregated (in_norm applied), fp16
__device__ __half g_w1h[F * F];
__device__ __half g_w2h[F * F];
__device__ float  g_vec[F];

// ---------------- setup ----------------
__global__ void k_count(const int* __restrict__ src, const int* __restrict__ dst) {
    int e = blockIdx.x * blockDim.x + threadIdx.x;
    if (e < N_EDGES) {
        atomicAdd(&g_deg_src[src[e]], 1);
        atomicAdd(&g_deg_dst[dst[e]], 1);
    }
}

// single-block CSR builder: prefix sum of deg_dst + norms + cursor init
__global__ void k_csr() {
    __shared__ int s[CSR_T];
    int t = threadIdx.x;
    int base = t * PER;
    int sum = 0;
    for (int j = 0; j < PER; j++) {
        int i = base + j;
        if (i < N_NODES) sum += g_deg_dst[i];
    }
    s[t] = sum;
    __syncthreads();
    for (int off = 1; off < CSR_T; off <<= 1) {
        int x = 0;
        if (t >= off) x = s[t - off];
        __syncthreads();
        if (t >= off) s[t] += x;
        __syncthreads();
    }
    int run = s[t] - sum;   // exclusive prefix
    for (int j = 0; j < PER; j++) {
        int i = base + j;
        if (i < N_NODES) {
            int d = g_deg_dst[i];
            g_row_ptr[i] = run;
            g_cursor[i] = run;
            run += d;
            g_in_norm[i]  = rsqrtf((float)max(d, 1));
            g_out_norm[i] = rsqrtf((float)max(g_deg_src[i], 1));
        }
    }
    if (t == CSR_T - 1) g_row_ptr[N_NODES] = s[t];
}

// CSR fill + feat->fp16 prescale + W1/W2 -> fp16
__global__ void k_fill_prep(const int* __restrict__ src, const int* __restrict__ dst,
                            const float* __restrict__ feat,
                            const float* __restrict__ W1, const float* __restrict__ W2) {
    int i = blockIdx.x * blockDim.x + threadIdx.x;
    if (i < N_EDGES) {
        int d = dst[i];
        int p = atomicAdd(&g_cursor[d], 1);
        g_col_idx[p] = src[i];
    }
    if (i < N_NODES * F / 4) {
        int base = i * 4;
        float on = g_out_norm[base >> 7];
        float4 v = *(const float4*)&feat[base];
        __half2 h01 = __floats2half2_rn(v.x * on, v.y * on);
        __half2 h23 = __floats2half2_rn(v.z * on, v.w * on);
        uint2 pk;
        pk.x = *(uint32_t*)&h01;
        pk.y = *(uint32_t*)&h23;
        *(uint2*)&g_x0[base] = pk;
    }
    if (i < F * F) {
        g_w1h[i] = __float2half(W1[i]);
        g_w2h[i] = __float2half(W2[i]);
    }
}

// ---------------- gather: warp per node, unroll 8, high occupancy ----------------
__global__ void __launch_bounds__(256)
k_agg(const __half* __restrict__ x, __half* __restrict__ m) {
    int w = (blockIdx.x * blockDim.x + threadIdx.x) >> 5;
    int lane = threadIdx.x & 31;
    if (w >= N_NODES) return;
    const uint2* x2 = (const uint2*)x;
    const int* __restrict__ ci = g_col_idx;
    int beg = g_row_ptr[w], end = g_row_ptr[w + 1];
    float4 a0 = {0.f, 0.f, 0.f, 0.f};
    float4 a1 = {0.f, 0.f, 0.f, 0.f};
    int e = beg;
    for (; e + 8 <= end; e += 8) {
        uint2 v[8];
#pragma unroll
        for (int j = 0; j < 8; j++) v[j] = x2[ci[e + j] * 32 + lane];
#pragma unroll
        for (int j = 0; j < 8; j++) {
            float2 pa = __half22float2(*(__half2*)&v[j].x);
            float2 pb = __half22float2(*(__half2*)&v[j].y);
            if (j & 1) { a1.x += pa.x; a1.y += pa.y; a1.z += pb.x; a1.w += pb.y; }
            else       { a0.x += pa.x; a0.y += pa.y; a0.z += pb.x; a0.w += pb.y; }
        }
    }
    for (; e < end; e++) {
        uint2 v = x2[ci[e] * 32 + lane];
        float2 pa = __half22float2(*(__half2*)&v.x);
        float2 pb = __half22float2(*(__half2*)&v.y);
        a0.x += pa.x; a0.y += pa.y; a0.z += pb.x; a0.w += pb.y;
    }
    float sc = g_in_norm[w];
    __half2 h01 = __floats2half2_rn((a0.x + a1.x) * sc, (a0.y + a1.y) * sc);
    __half2 h23 = __floats2half2_rn((a0.z + a1.z) * sc, (a0.w + a1.w) * sc);
    uint2 pk;
    pk.x = *(uint32_t*)&h01;
    pk.y = *(uint32_t*)&h23;
    ((uint2*)m)[w * 32 + lane] = pk;
}

// ---------------- GEMM: m @ W + b -> relu -> *out_norm -> fp16 ----------------
__global__ void __launch_bounds__(256, 3)
k_gemm(const __half* __restrict__ m, const __half* __restrict__ wh,
       const float* __restrict__ b, __half* __restrict__ y) {
    extern __shared__ char smem[];
    __half* sA = (__half*)smem;             // [GRM][LDA]
    int t = threadIdx.x, warp = t >> 5, lane = t & 31;
    int row0 = blockIdx.x * GRM;

    // stage A tile (coalesced uint4)
    const uint4* msrc = (const uint4*)(m + (size_t)row0 * F);
    for (int i = t; i < GRM * 16; i += 256) {
        int r = i >> 4, c = i & 15;
        uint4 v = {0u, 0u, 0u, 0u};
        if (row0 + r < N_NODES) v = msrc[r * 16 + c];
        *(uint4*)&sA[r * LDA + c * 8] = v;
    }
    __syncthreads();

    // warp (wy, wx): rows wy*32..+31, cols wx*32..+31; B from global fp16
    int wy = warp >> 2, wx = warp & 3;
    wmma::fragment<wmma::accumulator, 16, 16, 16, float> c[2][2];
#pragma unroll
    for (int i = 0; i < 2; i++)
#pragma unroll
        for (int j = 0; j < 2; j++) wmma::fill_fragment(c[i][j], 0.f);

#pragma unroll
    for (int k0 = 0; k0 < F; k0 += 16) {
        wmma::fragment<wmma::matrix_a, 16, 16, 16, __half, wmma::row_major> af[2];
        wmma::fragment<wmma::matrix_b, 16, 16, 16, __half, wmma::row_major> bf[2];
#pragma unroll
        for (int i = 0; i < 2; i++)
            wmma::load_matrix_sync(af[i], &sA[(wy * 32 + i * 16) * LDA + k0], LDA);
#pragma unroll
        for (int j = 0; j < 2; j++)
            wmma::load_matrix_sync(bf[j], &wh[k0 * F + wx * 32 + j * 16], F);
#pragma unroll
        for (int i = 0; i < 2; i++)
#pragma unroll
            for (int j = 0; j < 2; j++)
                wmma::mma_sync(c[i][j], af[i], bf[j], c[i][j]);
    }
    __syncthreads();   // done reading sA; reuse as epilogue scratch

    float* wscr = (float*)smem + warp * (16 * 20);   // 1280B per warp
#pragma unroll
    for (int i = 0; i < 2; i++) {
#pragma unroll
        for (int j = 0; j < 2; j++) {
            wmma::store_matrix_sync(wscr, c[i][j], 20, wmma::mem_row_major);
            __syncwarp();
            if (lane < 16) {
                int grow = row0 + wy * 32 + i * 16 + lane;
                if (grow < N_NODES) {
                    float on = g_out_norm[grow];
                    const float* cr = &wscr[lane * 20];
                    __half2 hv[8];
#pragma unroll
                    for (int cc = 0; cc < 16; cc += 4) {
                        float4 bv = *(const float4*)&b[wx * 32 + j * 16 + cc];
                        float v0 = fmaxf(cr[cc]     + bv.x, 0.f) * on;
                        float v1 = fmaxf(cr[cc + 1] + bv.y, 0.f) * on;
                        float v2 = fmaxf(cr[cc + 2] + bv.z, 0.f) * on;
                        float v3 = fmaxf(cr[cc + 3] + bv.w, 0.f) * on;
                        hv[cc / 2]     = __floats2half2_rn(v0, v1);
                        hv[cc / 2 + 1] = __floats2half2_rn(v2, v3);
                    }
                    uint4* dstp = (uint4*)(y + (size_t)grow * F + wx * 32 + j * 16);
                    dstp[0] = *(uint4*)&hv[0];
                    dstp[1] = *(uint4*)&hv[4];
                }
            }
            __syncwarp();
        }
    }
}

// ---------------- layer-3: edge-centric, no CSR, perfect balance ----------------
// g_vec = (1/N) * sum_e in_norm[dst_e] * x[src_e]   (x already * out_norm)
__global__ void __launch_bounds__(256)
k_agg3(const __half* __restrict__ x, const int* __restrict__ src,
       const int* __restrict__ dst) {
    __shared__ float sacc[F];
    int t = threadIdx.x;
    if (t < F) sacc[t] = 0.f;
    __syncthreads();
    int lane = t & 31;
    int gw = (blockIdx.x * blockDim.x + t) >> 5;
    int nw = gridDim.x * (blockDim.x >> 5);
    int per = (N_EDGES + nw - 1) / nw;
    int beg = gw * per;
    int end = min(beg + per, N_EDGES);
    const uint2* x2 = (const uint2*)x;
    float4 a0 = {0.f, 0.f, 0.f, 0.f};
    float4 a1 = {0.f, 0.f, 0.f, 0.f};
    int e = beg;
    for (; e + 4 <= end; e += 4) {
        int s[4], d[4];
#pragma unroll
        for (int j = 0; j < 4; j++) { s[j] = src[e + j]; d[j] = dst[e + j]; }
        float in[4];
        uint2 v[4];
#pragma unroll
        for (int j = 0; j < 4; j++) { in[j] = g_in_norm[d[j]]; v[j] = x2[s[j] * 32 + lane]; }
#pragma unroll
        for (int j = 0; j < 4; j++) {
            float2 pa = __half22float2(*(__half2*)&v[j].x);
            float2 pb = __half22float2(*(__half2*)&v[j].y);
            if (j & 1) { a1.x += in[j] * pa.x; a1.y += in[j] * pa.y; a1.z += in[j] * pb.x; a1.w += in[j] * pb.y; }
            else       { a0.x += in[j] * pa.x; a0.y += in[j] * pa.y; a0.z += in[j] * pb.x; a0.w += in[j] * pb.y; }
        }
    }
    for (; e < end; e++) {
        int s = src[e];
        float in = g_in_norm[dst[e]];
        uint2 v = x2[s * 32 + lane];
        float2 pa = __half22float2(*(__half2*)&v.x);
        float2 pb = __half22float2(*(__half2*)&v.y);
        a0.x += in * pa.x; a0.y += in * pa.y; a0.z += in * pb.x; a0.w += in * pb.y;
    }
    atomicAdd(&sacc[lane * 4 + 0], a0.x + a1.x);
    atomicAdd(&sacc[lane * 4 + 1], a0.y + a1.y);
    atomicAdd(&sacc[lane * 4 + 2], a0.z + a1.z);
    atomicAdd(&sacc[lane * 4 + 3], a0.w + a1.w);
    __syncthreads();
    if (t < F) atomicAdd(&g_vec[t], sacc[t] * (1.0f / N_NODES));
}

// final 128x128 matvec: out = g_vec @ W3 + b3 (fp32)
__global__ void k_final(const float* __restrict__ W3, const float* __restrict__ b3,
                        float* __restrict__ out) {
    __shared__ float sv[F];
    int j = threadIdx.x;
    sv[j] = g_vec[j];
    __syncthreads();
    float acc = b3[j];
#pragma unroll 8
    for (int k = 0; k < F; k++) acc += sv[k] * W3[k * F + j];
    out[j] = acc;
}

// zero state for NEXT replay
__global__ void k_tail() {
    int i = blockIdx.x * blockDim.x + threadIdx.x;
    if (i < N_NODES) { g_deg_src[i] = 0; g_deg_dst[i] = 0; }
    if (i < F) g_vec[i] = 0.f;
}

extern "C" void kernel_launch(void* const* d_in, const int* in_sizes, int n_in,
                              void* d_out, int out_size) {
    const float* feat = (const float*)d_in[0];
    const float* W1   = (const float*)d_in[1];
    const float* b1   = (const float*)d_in[2];
    const float* W2   = (const float*)d_in[3];
    const float* b2   = (const float*)d_in[4];
    const float* W3   = (const float*)d_in[5];
    const float* b3   = (const float*)d_in[6];
    const int*   src  = (const int*)d_in[7];
    const int*   dst  = (const int*)d_in[8];
    float* out = (float*)d_out;

    void *p0, *p1, *p2, *pm, *pw1, *pw2;
    cudaGetSymbolAddress(&p0, g_x0);
    cudaGetSymbolAddress(&p1, g_x1);
    cudaGetSymbolAddress(&p2, g_x2);
    cudaGetSymbolAddress(&pm, g_m);
    cudaGetSymbolAddress(&pw1, g_w1h);
    cudaGetSymbolAddress(&pw2, g_w2h);
    __half* x0 = (__half*)p0;
    __half* x1 = (__half*)p1;
    __half* x2 = (__half*)p2;
    __half* mm = (__half*)pm;
    __half* w1h = (__half*)pw1;
    __half* w2h = (__half*)pw2;

    int nb_nodes = (N_NODES + 255) / 256;
    int nb_edges = (N_EDGES + 255) / 256;
    int nb_aggw  = (N_NODES * 32 + 255) / 256;       // 6250 (warp per node)
    int nb_gemm  = (N_NODES + GRM - 1) / GRM;        // 782
    int nb_fp    = (N_NODES * F / 4 + 255) / 256;
    int nb_agg3  = 148 * 8;                          // even edge chunks

    // 1: degrees
    k_count<<<nb_edges, 256>>>(src, dst);
    // 2: CSR offsets + norms
    k_csr<<<1, CSR_T>>>();
    // 3: CSR fill + fp16 prescaled features + fp16 weights
    k_fill_prep<<<nb_fp, 256>>>(src, dst, feat, W1, W2);
    // 4: layer-1 gather (profiled by ncu)
    k_agg<<<nb_aggw, 256>>>(x0, mm);
    // 5: layer-1 GEMM
    k_gemm<<<nb_gemm, 256, SMEM_GEMM>>>(mm, w1h, b1, x1);
    // 6: layer-2 gather
    k_agg<<<nb_aggw, 256>>>(x1, mm);
    // 7: layer-2 GEMM
    k_gemm<<<nb_gemm, 256, SMEM_GEMM>>>(mm, w2h, b2, x2);
    // 8: layer-3 edge-centric fold into mean vector
    k_agg3<<<nb_agg3, 256>>>(x2, src, dst);
    // 9: final matvec
    k_final<<<1, F>>>(W3, b3, out);
    // 10: re-zero for next replay
    k_tail<<<nb_nodes, 256>>>();
}

// round 7
// speedup vs baseline: 1.8249x; 1.6928x over previous
#include <cuda_runtime.h>
#include <cuda_fp16.h>
#include <mma.h>
#include <cstdint>

using namespace nvcuda;

#define N_NODES 50000
#define N_EDGES 800000
#define F 128
#define GRM 64                  // rows per GEMM block
#define CH 256
#define NCH ((N_NODES + CH - 1) / CH)   // 196

// ---- scratch (no allocation allowed -> __device__ globals) ----
// deg arrays re-zeroed inside k_agg3; g_vec re-zeroed inside k_final.
// (module zero-init covers the very first run)
__device__ int    g_deg_src[N_NODES];
__device__ int    g_deg_dst[N_NODES];
__device__ float  g_out_norm[N_NODES];
__device__ float  g_in_norm[N_NODES];
__device__ int    g_row_ptr[N_NODES + 1];
__device__ int    g_cursor[N_NODES];
__device__ int    g_col_idx[N_EDGES];
__device__ int    g_chunk_sum[NCH];
__device__ __half g_x0[N_NODES * F];   // feat * out_norm, fp16
__device__ __half g_x1[N_NODES * F];
__device__ __half g_x2[N_NODES * F];
__device__ __half g_m[N_NODES * F];    // aggregated (in_norm applied), fp16
__device__ __half g_w1h[F * F];
__device__ __half g_w2h[F * F];
__device__ float  g_vec[F];

// ---------------- setup ----------------
__global__ void k_count(const int* __restrict__ src, const int* __restrict__ dst) {
    int e = blockIdx.x * blockDim.x + threadIdx.x;
    if (e < N_EDGES) {
        atomicAdd(&g_deg_src[src[e]], 1);
        atomicAdd(&g_deg_dst[dst[e]], 1);
    }
}

// block-local inclusive scan of deg_dst chunks
__global__ void k_scan1() {
    __shared__ int s[CH];
    int t = threadIdx.x;
    int i = blockIdx.x * CH + t;
    int v = (i < N_NODES) ? g_deg_dst[i] : 0;
    s[t] = v;
    __syncthreads();
    for (int off = 1; off < CH; off <<= 1) {
        int x = 0;
        if (t >= off) x = s[t - off];
        __syncthreads();
        if (t >= off) s[t] += x;
        __syncthreads();
    }
    if (i < N_NODES) g_row_ptr[i + 1] = s[t];
    if (t == CH - 1) g_chunk_sum[blockIdx.x] = s[t];
}

// finalize: each block scans the 196 chunk sums locally, then fixes its chunk
// + cursor + norms (rsqrtf spread over all SMs — NOT one block!)
__global__ void k_scan23() {
    __shared__ int s[CH];
    int t = threadIdx.x;
    int bid = blockIdx.x;
    int v = (t < NCH) ? g_chunk_sum[t] : 0;
    s[t] = v;
    __syncthreads();
    for (int off = 1; off < CH; off <<= 1) {
        int x = 0;
        if (t >= off) x = s[t - off];
        __syncthreads();
        if (t >= off) s[t] += x;
        __syncthreads();
    }
    int chunk_off = (bid > 0) ? s[bid - 1] : 0;
    int i = bid * CH + t;
    if (i < N_NODES) {
        int rp = g_row_ptr[i + 1] + chunk_off;
        g_row_ptr[i + 1] = rp;
        int d = g_deg_dst[i];
        g_cursor[i] = rp - d;
        g_in_norm[i]  = rsqrtf((float)max(d, 1));
        g_out_norm[i] = rsqrtf((float)max(g_deg_src[i], 1));
        if (i == 0) g_row_ptr[0] = 0;
    }
}

// CSR fill + feat->fp16 prescale + W1/W2 -> fp16
__global__ void k_fill_prep(const int* __restrict__ src, const int* __restrict__ dst,
                            const float* __restrict__ feat,
                            const float* __restrict__ W1, const float* __restrict__ W2) {
    int i = blockIdx.x * blockDim.x + threadIdx.x;
    if (i < N_EDGES) {
        int d = dst[i];
        int p = atomicAdd(&g_cursor[d], 1);
        g_col_idx[p] = src[i];
    }
    if (i < N_NODES * F / 4) {
        int base = i * 4;
        float on = g_out_norm[base >> 7];
        float4 v = *(const float4*)&feat[base];
        __half2 h01 = __floats2half2_rn(v.x * on, v.y * on);
        __half2 h23 = __floats2half2_rn(v.z * on, v.w * on);
        uint2 pk;
        pk.x = *(uint32_t*)&h01;
        pk.y = *(uint32_t*)&h23;
        *(uint2*)&g_x0[base] = pk;
    }
    if (i < F * F) {
        g_w1h[i] = __float2half(W1[i]);
        g_w2h[i] = __float2half(W2[i]);
    }
}

// ---------------- gather: warp per node, unroll 8 ----------------
__global__ void __launch_bounds__(256)
k_agg(const __half* __restrict__ x, __half* __restrict__ m) {
    int w = (blockIdx.x * blockDim.x + threadIdx.x) >> 5;
    int lane = threadIdx.x & 31;
    if (w >= N_NODES) return;
    const uint2* x2 = (const uint2*)x;
    const int* __restrict__ ci = g_col_idx;
    int beg = g_row_ptr[w], end = g_row_ptr[w + 1];
    float4 a0 = {0.f, 0.f, 0.f, 0.f};
    float4 a1 = {0.f, 0.f, 0.f, 0.f};
    int e = beg;
    for (; e + 8 <= end; e += 8) {
        uint2 v[8];
#pragma unroll
        for (int j = 0; j < 8; j++) v[j] = x2[ci[e + j] * 32 + lane];
#pragma unroll
        for (int j = 0; j < 8; j++) {
            float2 pa = __half22float2(*(__half2*)&v[j].x);
            float2 pb = __half22float2(*(__half2*)&v[j].y);
            if (j & 1) { a1.x += pa.x; a1.y += pa.y; a1.z += pb.x; a1.w += pb.y; }
            else       { a0.x += pa.x; a0.y += pa.y; a0.z += pb.x; a0.w += pb.y; }
        }
    }
    for (; e < end; e++) {
        uint2 v = x2[ci[e] * 32 + lane];
        float2 pa = __half22float2(*(__half2*)&v.x);
        float2 pb = __half22float2(*(__half2*)&v.y);
        a0.x += pa.x; a0.y += pa.y; a0.z += pb.x; a0.w += pb.y;
    }
    float sc = g_in_norm[w];
    __half2 h01 = __floats2half2_rn((a0.x + a1.x) * sc, (a0.y + a1.y) * sc);
    __half2 h23 = __floats2half2_rn((a0.z + a1.z) * sc, (a0.w + a1.w) * sc);
    uint2 pk;
    pk.x = *(uint32_t*)&h01;
    pk.y = *(uint32_t*)&h23;
    ((uint2*)m)[w * 32 + lane] = pk;
}

// ---------------- GEMM: m @ W + b -> relu -> *out_norm -> fp16 ----------------
// No smem staging: wmma fragments loaded straight from global (L1/L2 resident).
// Per-warp smem scratch for epilogue only (no block-wide syncs).
__global__ void __launch_bounds__(256)
k_gemm(const __half* __restrict__ m, const __half* __restrict__ wh,
       const float* __restrict__ b, __half* __restrict__ y) {
    __shared__ float scr[8][16 * 20];   // per-warp epilogue scratch (10.2KB)
    int t = threadIdx.x, warp = t >> 5, lane = t & 31;
    int row0 = blockIdx.x * GRM;
    int wy = warp >> 2, wx = warp & 3;   // rows wy*32.., cols wx*32..
    int arow = row0 + wy * 32;

    wmma::fragment<wmma::accumulator, 16, 16, 16, float> c[2][2];
#pragma unroll
    for (int i = 0; i < 2; i++)
#pragma unroll
        for (int j = 0; j < 2; j++) wmma::fill_fragment(c[i][j], 0.f);

#pragma unroll
    for (int k0 = 0; k0 < F; k0 += 16) {
        wmma::fragment<wmma::matrix_a, 16, 16, 16, __half, wmma::row_major> af[2];
        wmma::fragment<wmma::matrix_b, 16, 16, 16, __half, wmma::row_major> bf[2];
#pragma unroll
        for (int i = 0; i < 2; i++)
            wmma::load_matrix_sync(af[i], &m[(size_t)(arow + i * 16) * F + k0], F);
#pragma unroll
        for (int j = 0; j < 2; j++)
            wmma::load_matrix_sync(bf[j], &wh[k0 * F + wx * 32 + j * 16], F);
#pragma unroll
        for (int i = 0; i < 2; i++)
#pragma unroll
            for (int j = 0; j < 2; j++)
                wmma::mma_sync(c[i][j], af[i], bf[j], c[i][j]);
    }

    float* wscr = scr[warp];
#pragma unroll
    for (int i = 0; i < 2; i++) {
#pragma unroll
        for (int j = 0; j < 2; j++) {
            wmma::store_matrix_sync(wscr, c[i][j], 20, wmma::mem_row_major);
            __syncwarp();
            if (lane < 16) {
                int grow = arow + i * 16 + lane;
                if (grow < N_NODES) {
                    float on = g_out_norm[grow];
                    const float* cr = &wscr[lane * 20];
                    __half2 hv[8];
#pragma unroll
                    for (int cc = 0; cc < 16; cc += 4) {
                        float4 bv = *(const float4*)&b[wx * 32 + j * 16 + cc];
                        float v0 = fmaxf(cr[cc]     + bv.x, 0.f) * on;
                        float v1 = fmaxf(cr[cc + 1] + bv.y, 0.f) * on;
                        float v2 = fmaxf(cr[cc + 2] + bv.z, 0.f) * on;
                        float v3 = fmaxf(cr[cc + 3] + bv.w, 0.f) * on;
                        hv[cc / 2]     = __floats2half2_rn(v0, v1);
                        hv[cc / 2 + 1] = __floats2half2_rn(v2, v3);
                    }
                    uint4* dstp = (uint4*)(y + (size_t)grow * F + wx * 32 + j * 16);
                    dstp[0] = *(uint4*)&hv[0];
                    dstp[1] = *(uint4*)&hv[4];
                }
            }
            __syncwarp();
        }
    }
}

// ---------------- layer-3: edge-centric + fold deg re-zero ----------------
// g_vec = (1/N) * sum_e in_norm[dst_e] * x[src_e]   (x already * out_norm)
__global__ void __launch_bounds__(256)
k_agg3(const __half* __restrict__ x, const int* __restrict__ src,
       const int* __restrict__ dst) {
    // re-zero degree arrays for next replay (no longer read this replay)
    int gid = blockIdx.x * blockDim.x + threadIdx.x;
    if (gid < N_NODES) { g_deg_src[gid] = 0; g_deg_dst[gid] = 0; }

    __shared__ float sacc[F];
    int t = threadIdx.x;
    if (t < F) sacc[t] = 0.f;
    __syncthreads();
    int lane = t & 31;
    int gw = gid >> 5;
    int nw = gridDim.x * (blockDim.x >> 5);
    int per = (N_EDGES + nw - 1) / nw;
    int beg = gw * per;
    int end = min(beg + per, N_EDGES);
    const uint2* x2 = (const uint2*)x;
    float4 a0 = {0.f, 0.f, 0.f, 0.f};
    float4 a1 = {0.f, 0.f, 0.f, 0.f};
    int e = beg;
    for (; e + 4 <= end; e += 4) {
        int s[4], d[4];
#pragma unroll
        for (int j = 0; j < 4; j++) { s[j] = src[e + j]; d[j] = dst[e + j]; }
        float in[4];
        uint2 v[4];
#pragma unroll
        for (int j = 0; j < 4; j++) { in[j] = g_in_norm[d[j]]; v[j] = x2[s[j] * 32 + lane]; }
#pragma unroll
        for (int j = 0; j < 4; j++) {
            float2 pa = __half22float2(*(__half2*)&v[j].x);
            float2 pb = __half22float2(*(__half2*)&v[j].y);
            if (j & 1) { a1.x += in[j] * pa.x; a1.y += in[j] * pa.y; a1.z += in[j] * pb.x; a1.w += in[j] * pb.y; }
            else       { a0.x += in[j] * pa.x; a0.y += in[j] * pa.y; a0.z += in[j] * pb.x; a0.w += in[j] * pb.y; }
        }
    }
    for (; e < end; e++) {
        int s = src[e];
        float in = g_in_norm[dst[e]];
        uint2 v = x2[s * 32 + lane];
        float2 pa = __half22float2(*(__half2*)&v.x);
        float2 pb = __half22float2(*(__half2*)&v.y);
        a0.x += in * pa.x; a0.y += in * pa.y; a0.z += in * pb.x; a0.w += in * pb.y;
    }
    atomicAdd(&sacc[lane * 4 + 0], a0.x + a1.x);
    atomicAdd(&sacc[lane * 4 + 1], a0.y + a1.y);
    atomicAdd(&sacc[lane * 4 + 2], a0.z + a1.z);
    atomicAdd(&sacc[lane * 4 + 3], a0.w + a1.w);
    __syncthreads();
    if (t < F) atomicAdd(&g_vec[t], sacc[t] * (1.0f / N_NODES));
}

// final matvec: out = g_vec @ W3 + b3; then re-zero g_vec for next replay
__global__ void k_final(const float* __restrict__ W3, const float* __restrict__ b3,
                        float* __restrict__ out) {
    __shared__ float sv[F];
    int j = threadIdx.x;
    sv[j] = g_vec[j];
    __syncthreads();
    g_vec[j] = 0.f;
    float acc = b3[j];
#pragma unroll 8
    for (int k = 0; k < F; k++) acc += sv[k] * W3[k * F + j];
    out[j] = acc;
}

extern "C" void kernel_launch(void* const* d_in, const int* in_sizes, int n_in,
                              void* d_out, int out_size) {
    const float* feat = (const float*)d_in[0];
    const float* W1   = (const float*)d_in[1];
    const float* b1   = (const float*)d_in[2];
    const float* W2   = (const float*)d_in[3];
    const float* b2   = (const float*)d_in[4];
    const float* W3   = (const float*)d_in[5];
    const float* b3   = (const float*)d_in[6];
    const int*   src  = (const int*)d_in[7];
    const int*   dst  = (const int*)d_in[8];
    float* out = (float*)d_out;

    void *p0, *p1, *p2, *pm, *pw1, *pw2;
    cudaGetSymbolAddress(&p0, g_x0);
    cudaGetSymbolAddress(&p1, g_x1);
    cudaGetSymbolAddress(&p2, g_x2);
    cudaGetSymbolAddress(&pm, g_m);
    cudaGetSymbolAddress(&pw1, g_w1h);
    cudaGetSymbolAddress(&pw2, g_w2h);
    __half* x0 = (__half*)p0;
    __half* x1 = (__half*)p1;
    __half* x2 = (__half*)p2;
    __half* mm = (__half*)pm;
    __half* w1h = (__half*)pw1;
    __half* w2h = (__half*)pw2;

    int nb_edges = (N_EDGES + 255) / 256;
    int nb_aggw  = (N_NODES * 32 + 255) / 256;       // 6250 (warp per node)
    int nb_gemm  = (N_NODES + GRM - 1) / GRM;        // 782
    int nb_fp    = (N_NODES * F / 4 + 255) / 256;
    int nb_agg3  = 148 * 8;

    // 1: degrees
    k_count<<<nb_edges, 256>>>(src, dst);
    // 2-3: CSR offsets + norms (multi-block; rsqrt spread over SMs)
    k_scan1<<<NCH, CH>>>();
    k_scan23<<<NCH, CH>>>();
    // 4: CSR fill + fp16 features + fp16 weights (profiled by ncu)
    k_fill_prep<<<nb_fp, 256>>>(src, dst, feat, W1, W2);
    // 5-8: layers 1-2
    k_agg<<<nb_aggw, 256>>>(x0, mm);
    k_gemm<<<nb_gemm, 256>>>(mm, w1h, b1, x1);
    k_agg<<<nb_aggw, 256>>>(x1, mm);
    k_gemm<<<nb_gemm, 256>>>(mm, w2h, b2, x2);
    // 9: layer-3 edge-centric fold into mean vector (+ deg re-zero)
    k_agg3<<<nb_agg3, 256>>>(x2, src, dst);
    // 10: final matvec (+ g_vec re-zero)
    k_final<<<1, F>>>(W3, b3, out);
}

// round 8
// speedup vs baseline: 2.3189x; 1.2707x over previous
#include <cuda_runtime.h>
#include <cuda_fp16.h>
#include <mma.h>
#include <cstdint>

using namespace nvcuda;

#define N_NODES 50000
#define N_EDGES 800000
#define F 128
#define GRM 128                 // rows per GEMM block
#define LDA 136                 // padded leading dim (halves)
#define CH 256
#define NCH ((N_NODES + CH - 1) / CH)   // 196
#define SMEM_GEMM (2 * GRM * LDA * 2)   // A + B tiles: 69632 B

// ---- scratch (no allocation allowed -> __device__ globals) ----
// deg arrays re-zeroed inside k_agg3; g_vec re-zeroed inside k_final.
__device__ int    g_deg_src[N_NODES];
__device__ int    g_deg_dst[N_NODES];
__device__ float  g_out_norm[N_NODES];
__device__ float  g_in_norm[N_NODES];
__device__ int    g_row_ptr[N_NODES + 1];
__device__ int    g_cursor[N_NODES];
__device__ int    g_col_idx[N_EDGES];
__device__ int    g_chunk_sum[NCH];
__device__ __half g_x0[N_NODES * F];
__device__ __half g_x1[N_NODES * F];
__device__ __half g_x2[N_NODES * F];
__device__ __half g_m[N_NODES * F];
__device__ __half g_w1h[F * F];
__device__ __half g_w2h[F * F];
__device__ float  g_vec[F];

// ---------------- setup ----------------
__global__ void k_count(const int* __restrict__ src, const int* __restrict__ dst) {
    int e = blockIdx.x * blockDim.x + threadIdx.x;
    if (e < N_EDGES) {
        atomicAdd(&g_deg_src[src[e]], 1);
        atomicAdd(&g_deg_dst[dst[e]], 1);
    }
}

__global__ void k_scan1() {
    __shared__ int s[CH];
    int t = threadIdx.x;
    int i = blockIdx.x * CH + t;
    int v = (i < N_NODES) ? g_deg_dst[i] : 0;
    s[t] = v;
    __syncthreads();
    for (int off = 1; off < CH; off <<= 1) {
        int x = 0;
        if (t >= off) x = s[t - off];
        __syncthreads();
        if (t >= off) s[t] += x;
        __syncthreads();
    }
    if (i < N_NODES) g_row_ptr[i + 1] = s[t];
    if (t == CH - 1) g_chunk_sum[blockIdx.x] = s[t];
}

// finalize: each block re-scans chunk sums locally; rsqrt spread over SMs
__global__ void k_scan23() {
    __shared__ int s[CH];
    int t = threadIdx.x;
    int bid = blockIdx.x;
    int v = (t < NCH) ? g_chunk_sum[t] : 0;
    s[t] = v;
    __syncthreads();
    for (int off = 1; off < CH; off <<= 1) {
        int x = 0;
        if (t >= off) x = s[t - off];
        __syncthreads();
        if (t >= off) s[t] += x;
        __syncthreads();
    }
    int chunk_off = (bid > 0) ? s[bid - 1] : 0;
    int i = bid * CH + t;
    if (i < N_NODES) {
        int rp = g_row_ptr[i + 1] + chunk_off;
        g_row_ptr[i + 1] = rp;
        int d = g_deg_dst[i];
        g_cursor[i] = rp - d;
        g_in_norm[i]  = rsqrtf((float)max(d, 1));
        g_out_norm[i] = rsqrtf((float)max(g_deg_src[i], 1));
        if (i == 0) g_row_ptr[0] = 0;
    }
}

__global__ void k_fill_prep(const int* __restrict__ src, const int* __restrict__ dst,
                            const float* __restrict__ feat,
                            const float* __restrict__ W1, const float* __restrict__ W2) {
    int i = blockIdx.x * blockDim.x + threadIdx.x;
    if (i < N_EDGES) {
        int d = dst[i];
        int p = atomicAdd(&g_cursor[d], 1);
        g_col_idx[p] = src[i];
    }
    if (i < N_NODES * F / 4) {
        int base = i * 4;
        float on = g_out_norm[base >> 7];
        float4 v = *(const float4*)&feat[base];
        __half2 h01 = __floats2half2_rn(v.x * on, v.y * on);
        __half2 h23 = __floats2half2_rn(v.z * on, v.w * on);
        uint2 pk;
        pk.x = *(uint32_t*)&h01;
        pk.y = *(uint32_t*)&h23;
        *(uint2*)&g_x0[base] = pk;
    }
    if (i < F * F) {
        g_w1h[i] = __float2half(W1[i]);
        g_w2h[i] = __float2half(W2[i]);
    }
}

// ---------------- gather: warp per node, unroll 8 ----------------
__global__ void __launch_bounds__(256)
k_agg(const __half* __restrict__ x, __half* __restrict__ m) {
    int w = (blockIdx.x * blockDim.x + threadIdx.x) >> 5;
    int lane = threadIdx.x & 31;
    if (w >= N_NODES) return;
    const uint2* x2 = (const uint2*)x;
    const int* __restrict__ ci = g_col_idx;
    int beg = g_row_ptr[w], end = g_row_ptr[w + 1];
    float4 a0 = {0.f, 0.f, 0.f, 0.f};
    float4 a1 = {0.f, 0.f, 0.f, 0.f};
    int e = beg;
    for (; e + 8 <= end; e += 8) {
        uint2 v[8];
#pragma unroll
        for (int j = 0; j < 8; j++) v[j] = x2[ci[e + j] * 32 + lane];
#pragma unroll
        for (int j = 0; j < 8; j++) {
            float2 pa = __half22float2(*(__half2*)&v[j].x);
            float2 pb = __half22float2(*(__half2*)&v[j].y);
            if (j & 1) { a1.x += pa.x; a1.y += pa.y; a1.z += pb.x; a1.w += pb.y; }
            else       { a0.x += pa.x; a0.y += pa.y; a0.z += pb.x; a0.w += pb.y; }
        }
    }
    for (; e < end; e++) {
        uint2 v = x2[ci[e] * 32 + lane];
        float2 pa = __half22float2(*(__half2*)&v.x);
        float2 pb = __half22float2(*(__half2*)&v.y);
        a0.x += pa.x; a0.y += pa.y; a0.z += pb.x; a0.w += pb.y;
    }
    float sc = g_in_norm[w];
    __half2 h01 = __floats2half2_rn((a0.x + a1.x) * sc, (a0.y + a1.y) * sc);
    __half2 h23 = __floats2half2_rn((a0.z + a1.z) * sc, (a0.w + a1.w) * sc);
    uint2 pk;
    pk.x = *(uint32_t*)&h01;
    pk.y = *(uint32_t*)&h23;
    ((uint2*)m)[w * 32 + lane] = pk;
}

// ---------------- GEMM: m @ W + b -> relu -> *out_norm -> fp16 ----------------
// 128 rows/block; W and A staged in smem (coalesced); warp tile 32x64.
__global__ void __launch_bounds__(256, 2)
k_gemm(const __half* __restrict__ m, const __half* __restrict__ wh,
       const float* __restrict__ b, __half* __restrict__ y) {
    extern __shared__ char smem[];
    __half* sA = (__half*)smem;                        // [128][LDA]
    __half* sB = (__half*)(smem + GRM * LDA * 2);      // [128][LDA]
    int t = threadIdx.x, warp = t >> 5, lane = t & 31;
    int row0 = blockIdx.x * GRM;

    // stage A (128x128 fp16) and B=W (128x128 fp16), coalesced uint4
    {
        const uint4* asrc = (const uint4*)(m + (size_t)row0 * F);
        const uint4* bsrc = (const uint4*)wh;
        for (int i = t; i < GRM * 16; i += 256) {
            int r = i >> 4, c = i & 15;
            uint4 av = {0u, 0u, 0u, 0u};
            if (row0 + r < N_NODES) av = asrc[i];
            *(uint4*)&sA[r * LDA + c * 8] = av;
            *(uint4*)&sB[r * LDA + c * 8] = bsrc[i];
        }
    }
    __syncthreads();

    // warp tile: rows (warp>>1)*32 .. +31, cols (warp&1)*64 .. +63
    int wy = warp >> 1, wx = warp & 1;
    wmma::fragment<wmma::accumulator, 16, 16, 16, float> c[2][4];
#pragma unroll
    for (int i = 0; i < 2; i++)
#pragma unroll
        for (int j = 0; j < 4; j++) wmma::fill_fragment(c[i][j], 0.f);

#pragma unroll
    for (int k0 = 0; k0 < F; k0 += 16) {
        wmma::fragment<wmma::matrix_a, 16, 16, 16, __half, wmma::row_major> af[2];
        wmma::fragment<wmma::matrix_b, 16, 16, 16, __half, wmma::row_major> bf[4];
#pragma unroll
        for (int i = 0; i < 2; i++)
            wmma::load_matrix_sync(af[i], &sA[(wy * 32 + i * 16) * LDA + k0], LDA);
#pragma unroll
        for (int j = 0; j < 4; j++)
            wmma::load_matrix_sync(bf[j], &sB[k0 * LDA + wx * 64 + j * 16], LDA);
#pragma unroll
        for (int i = 0; i < 2; i++)
#pragma unroll
            for (int j = 0; j < 4; j++)
                wmma::mma_sync(c[i][j], af[i], bf[j], c[i][j]);
    }
    __syncthreads();   // done reading sA/sB; reuse sA as epilogue scratch

    float* wscr = (float*)smem + warp * (16 * 20);     // 1280B per warp
#pragma unroll
    for (int i = 0; i < 2; i++) {
#pragma unroll
        for (int j = 0; j < 4; j++) {
            wmma::store_matrix_sync(wscr, c[i][j], 20, wmma::mem_row_major);
            __syncwarp();
            if (lane < 16) {
                int grow = row0 + wy * 32 + i * 16 + lane;
                if (grow < N_NODES) {
                    float on = g_out_norm[grow];
                    const float* cr = &wscr[lane * 20];
                    __half2 hv[8];
#pragma unroll
                    for (int cc = 0; cc < 16; cc += 4) {
                        float4 bv = *(const float4*)&b[wx * 64 + j * 16 + cc];
                        float v0 = fmaxf(cr[cc]     + bv.x, 0.f) * on;
                        float v1 = fmaxf(cr[cc + 1] + bv.y, 0.f) * on;
                        float v2 = fmaxf(cr[cc + 2] + bv.z, 0.f) * on;
                        float v3 = fmaxf(cr[cc + 3] + bv.w, 0.f) * on;
                        hv[cc / 2]     = __floats2half2_rn(v0, v1);
                        hv[cc / 2 + 1] = __floats2half2_rn(v2, v3);
                    }
                    uint4* dstp = (uint4*)(y + (size_t)grow * F + wx * 64 + j * 16);
                    dstp[0] = *(uint4*)&hv[0];
                    dstp[1] = *(uint4*)&hv[4];
                }
            }
            __syncwarp();
        }
    }
}

// ---------------- layer-3: edge-centric + deg re-zero ----------------
__global__ void __launch_bounds__(256)
k_agg3(const __half* __restrict__ x, const int* __restrict__ src,
       const int* __restrict__ dst) {
    int gid = blockIdx.x * blockDim.x + threadIdx.x;
    if (gid < N_NODES) { g_deg_src[gid] = 0; g_deg_dst[gid] = 0; }

    __shared__ float sacc[F];
    int t = threadIdx.x;
    if (t < F) sacc[t] = 0.f;
    __syncthreads();
    int lane = t & 31;
    int gw = gid >> 5;
    int nw = gridDim.x * (blockDim.x >> 5);
    int per = (N_EDGES + nw - 1) / nw;
    int beg = gw * per;
    int end = min(beg + per, N_EDGES);
    const uint2* x2 = (const uint2*)x;
    float4 a0 = {0.f, 0.f, 0.f, 0.f};
    float4 a1 = {0.f, 0.f, 0.f, 0.f};
    int e = beg;
    for (; e + 4 <= end; e += 4) {
        int s[4], d[4];
#pragma unroll
        for (int j = 0; j < 4; j++) { s[j] = src[e + j]; d[j] = dst[e + j]; }
        float in[4];
        uint2 v[4];
#pragma unroll
        for (int j = 0; j < 4; j++) { in[j] = g_in_norm[d[j]]; v[j] = x2[s[j] * 32 + lane]; }
#pragma unroll
        for (int j = 0; j < 4; j++) {
            float2 pa = __half22float2(*(__half2*)&v[j].x);
            float2 pb = __half22float2(*(__half2*)&v[j].y);
            if (j & 1) { a1.x += in[j] * pa.x; a1.y += in[j] * pa.y; a1.z += in[j] * pb.x; a1.w += in[j] * pb.y; }
            else       { a0.x += in[j] * pa.x; a0.y += in[j] * pa.y; a0.z += in[j] * pb.x; a0.w += in[j] * pb.y; }
        }
    }
    for (; e < end; e++) {
        int s = src[e];
        float in = g_in_norm[dst[e]];
        uint2 v = x2[s * 32 + lane];
        float2 pa = __half22float2(*(__half2*)&v.x);
        float2 pb = __half22float2(*(__half2*)&v.y);
        a0.x += in * pa.x; a0.y += in * pa.y; a0.z += in * pb.x; a0.w += in * pb.y;
    }
    atomicAdd(&sacc[lane * 4 + 0], a0.x + a1.x);
    atomicAdd(&sacc[lane * 4 + 1], a0.y + a1.y);
    atomicAdd(&sacc[lane * 4 + 2], a0.z + a1.z);
    atomicAdd(&sacc[lane * 4 + 3], a0.w + a1.w);
    __syncthreads();
    if (t < F) atomicAdd(&g_vec[t], sacc[t] * (1.0f / N_NODES));
}

// final matvec + g_vec re-zero
__global__ void k_final(const float* __restrict__ W3, const float* __restrict__ b3,
                        float* __restrict__ out) {
    __shared__ float sv[F];
    int j = threadIdx.x;
    sv[j] = g_vec[j];
    __syncthreads();
    g_vec[j] = 0.f;
    float acc = b3[j];
#pragma unroll 8
    for (int k = 0; k < F; k++) acc += sv[k] * W3[k * F + j];
    out[j] = acc;
}

extern "C" void kernel_launch(void* const* d_in, const int* in_sizes, int n_in,
                              void* d_out, int out_size) {
    const float* feat = (const float*)d_in[0];
    const float* W1   = (const float*)d_in[1];
    const float* b1   = (const float*)d_in[2];
    const float* W2   = (const float*)d_in[3];
    const float* b2   = (const float*)d_in[4];
    const float* W3   = (const float*)d_in[5];
    const float* b3   = (const float*)d_in[6];
    const int*   src  = (const int*)d_in[7];
    const int*   dst  = (const int*)d_in[8];
    float* out = (float*)d_out;

    cudaFuncSetAttribute(k_gemm, cudaFuncAttributeMaxDynamicSharedMemorySize, SMEM_GEMM);

    void *p0, *p1, *p2, *pm, *pw1, *pw2;
    cudaGetSymbolAddress(&p0, g_x0);
    cudaGetSymbolAddress(&p1, g_x1);
    cudaGetSymbolAddress(&p2, g_x2);
    cudaGetSymbolAddress(&pm, g_m);
    cudaGetSymbolAddress(&pw1, g_w1h);
    cudaGetSymbolAddress(&pw2, g_w2h);
    __half* x0 = (__half*)p0;
    __half* x1 = (__half*)p1;
    __half* x2 = (__half*)p2;
    __half* mm = (__half*)pm;
    __half* w1h = (__half*)pw1;
    __half* w2h = (__half*)pw2;

    int nb_edges = (N_EDGES + 255) / 256;
    int nb_aggw  = (N_NODES * 32 + 255) / 256;       // 6250
    int nb_gemm  = (N_NODES + GRM - 1) / GRM;        // 391
    int nb_fp    = (N_NODES * F / 4 + 255) / 256;
    int nb_agg3  = 148 * 8;

    k_count<<<nb_edges, 256>>>(src, dst);
    k_scan1<<<NCH, CH>>>();
    k_scan23<<<NCH, CH>>>();
    k_fill_prep<<<nb_fp, 256>>>(src, dst, feat, W1, W2);   // profiled (#4)
    k_agg<<<nb_aggw, 256>>>(x0, mm);
    k_gemm<<<nb_gemm, 256, SMEM_GEMM>>>(mm, w1h, b1, x1);
    k_agg<<<nb_aggw, 256>>>(x1, mm);
    k_gemm<<<nb_gemm, 256, SMEM_GEMM>>>(mm, w2h, b2, x2);
    k_agg3<<<nb_agg3, 256>>>(x2, src, dst);
    k_final<<<1, F>>>(W3, b3, out);
}